// round 1
// baseline (speedup 1.0000x reference)
#include <cuda_runtime.h>
#include <cuda_bf16.h>

// FlowEmbedder cost kernel.
//
// Math: cost_i = sum_{s=0}^{n_i-1} STEP / normalizer(dot_{i,s})
//   normalizer = F*e/(F-1+e), e = exp(dot)
//   => STEP/normalizer = STEP/F + STEP*(F-1)/F * exp(-dot) = 0.02 + 0.08*exp(-dot)
//   dot_{i,s} = c0*x^3 + c1*x^2*y + c2*x*y^2 with c_k = comb_k * (p_k . d_i)
//   x(s) = X + s*H, y(s) = Y + s*G  (H = 0.1*dx/euc, G = 0.1*dy/euc)
//   => exponent g(s) (already scaled by -log2 e) is an exact cubic in s:
//      g(s) = k0 + k1 s + k2 s^2 + k3 s^3, evaluated by Horner (3 FMA/step),
//      exp(-dot) = ex2(g).
//   n_i = floor(euc/0.1) + 1  (<= 15 for points in [0,1)^2; clamp to 16)

__device__ __forceinline__ float cubic_val(float c0, float c1, float c2,
                                           float x, float y) {
    // c0*x^3 + c1*x^2*y + c2*x*y^2 = x*(c0*x^2 + c1*x*y + c2*y^2)
    float xx = x * x;
    float xy = x * y;
    float yy = y * y;
    return x * fmaf(c0, xx, fmaf(c1, xy, c2 * yy));
}

__device__ __forceinline__ float k_odd(float c0, float c1, float c2,
                                       float X, float Y, float H, float G) {
    // s^1 coefficient of c0*x^3 + c1*x^2*y + c2*x*y^2 with x=X+sH, y=Y+sG:
    //   c0*3X^2H + c1*(2XYH + X^2 G) + c2*(Y^2 H + 2XYG)
    // (the s^2 coefficient is the same expression with (X,Y) <-> (H,G))
    float XX = X * X;
    float XY = X * Y;
    float YY = Y * Y;
    float t0 = 3.0f * XX * H;
    float t1 = fmaf(2.0f * XY, H, XX * G);
    float t2 = fmaf(YY, H, 2.0f * XY * G);
    return fmaf(c0, t0, fmaf(c1, t1, c2 * t2));
}

__global__ void __launch_bounds__(256)
flow_cost_kernel(const float2* __restrict__ x1,
                 const float2* __restrict__ x2,
                 const float* __restrict__ pp,
                 float* __restrict__ out,
                 int n_pairs) {
    int i = blockIdx.x * blockDim.x + threadIdx.x;
    if (i >= n_pairs) return;

    float2 a = x1[i];
    float2 b = x2[i];
    float dx = b.x - a.x;
    float dy = b.y - a.y;

    // euc and n must match the reference's IEEE fp32 ops exactly (floor branch).
    float euc = __fsqrt_rn(dx * dx + dy * dy);
    int n = (int)floorf(__fdiv_rn(euc, 0.1f)) + 1;
    n = min(n, 16);

    float inv = __fdiv_rn(1.0f, euc);
    float H = 0.1f * dx * inv;   // per-step x displacement
    float G = 0.1f * dy * inv;   // per-step y displacement

    // Fold flow params, binomial coeffs and -log2(e) into per-pair scalars.
    const float NL2E = -1.4426950408889634f;
    float p00 = pp[0], p01 = pp[1];
    float p10 = pp[2], p11 = pp[3];
    float p20 = pp[4], p21 = pp[5];
    float c0 = NL2E * fmaf(p00, dx, p01 * dy);
    float c1 = (3.0f * NL2E) * fmaf(p10, dx, p11 * dy);
    float c2 = (3.0f * NL2E) * fmaf(p20, dx, p21 * dy);

    float X = a.x, Y = a.y;

    // Exact cubic-in-s coefficients of the (log2-domain) exponent.
    float k0 = cubic_val(c0, c1, c2, X, Y);
    float k3 = cubic_val(c0, c1, c2, H, G);
    float k1 = k_odd(c0, c1, c2, X, Y, H, G);
    float k2 = k_odd(c0, c1, c2, H, G, X, Y);

    float acc = 0.0f;
    float sf = 0.0f;
    for (int s = 0; s < n; ++s) {
        float g = fmaf(fmaf(fmaf(k3, sf, k2), sf, k1), sf, k0);
        float e;
        asm("ex2.approx.f32 %0, %1;" : "=f"(e) : "f"(g));
        acc += e;
        sf += 1.0f;
    }

    out[i] = fmaf(0.08f, acc, 0.02f * (float)n);
}

extern "C" void kernel_launch(void* const* d_in, const int* in_sizes, int n_in,
                              void* d_out, int out_size) {
    const float2* x1 = (const float2*)d_in[0];
    const float2* x2 = (const float2*)d_in[1];
    const float*  pp = (const float*)d_in[2];
    float* out = (float*)d_out;

    int n_pairs = out_size;  // one cost per pair
    int threads = 256;
    int blocks = (n_pairs + threads - 1) / threads;
    flow_cost_kernel<<<blocks, threads>>>(x1, x2, pp, out, n_pairs);
}

// round 2
// speedup vs baseline: 1.1133x; 1.1133x over previous
#include <cuda_runtime.h>
#include <cuda_bf16.h>

// FlowEmbedder cost kernel, round 2.
//
// cost_i = 0.02*n_i + 0.08 * sum_{s=0}^{n_i-1} exp(-dot_{i,s})
// with dot a cubic polynomial in s (exact coefficients k0..k3), evaluated
// fully unrolled so every Horner FMA has an immediate multiplier (FFMA-imm,
// rt=1 on sm_103a) and exp(-dot) = ex2(g) with g pre-scaled by -log2(e).
// n_i = floor(euc/0.1)+1 uses bit-identical IEEE sqrt+div to round 1.

__device__ __forceinline__ float cubic_val(float c0, float c1, float c2,
                                           float x, float y) {
    // c0*x^3 + c1*x^2*y + c2*x*y^2
    float xx = x * x;
    float xy = x * y;
    float yy = y * y;
    return x * fmaf(c0, xx, fmaf(c1, xy, c2 * yy));
}

__device__ __forceinline__ float k_odd(float c0, float c1, float c2,
                                       float X, float Y, float H, float G) {
    // s^1 coefficient (s^2 coefficient = same with (X,Y)<->(H,G))
    float XX = X * X;
    float XY = X * Y;
    float YY = Y * Y;
    float t0 = 3.0f * XX * H;
    float t1 = fmaf(2.0f * XY, H, XX * G);
    float t2 = fmaf(YY, H, 2.0f * XY * G);
    return fmaf(c0, t0, fmaf(c1, t1, c2 * t2));
}

__device__ __forceinline__ float pair_cost(float ax, float ay, float bx, float by,
                                           float p00, float p01, float p10,
                                           float p11, float p20, float p21) {
    float dx = bx - ax;
    float dy = by - ay;

    // Bit-identical to round 1 (passed at 8e-8): IEEE sqrt + IEEE div for the
    // discrete floor() branch.
    float euc = __fsqrt_rn(dx * dx + dy * dy);
    int n = (int)floorf(__fdiv_rn(euc, 0.1f)) + 1;  // <= 15 in [0,1)^2

    // 1/euc only scales H,G (smooth path) -> fast MUFU rcp is plenty.
    float inv;
    asm("rcp.approx.f32 %0, %1;" : "=f"(inv) : "f"(euc));
    float H = 0.1f * dx * inv;
    float G = 0.1f * dy * inv;

    const float NL2E = -1.4426950408889634f;  // -log2(e)
    float c0 = NL2E * fmaf(p00, dx, p01 * dy);
    float c1 = (3.0f * NL2E) * fmaf(p10, dx, p11 * dy);
    float c2 = (3.0f * NL2E) * fmaf(p20, dx, p21 * dy);

    float X = ax, Y = ay;
    float k0 = cubic_val(c0, c1, c2, X, Y);
    float k3 = cubic_val(c0, c1, c2, H, G);
    float k1 = k_odd(c0, c1, c2, X, Y, H, G);
    float k2 = k_odd(c0, c1, c2, H, G, X, Y);

    float acc0 = 0.0f, acc1 = 0.0f;
#pragma unroll
    for (int s = 0; s < 16; s += 2) {
        float s0 = (float)s;
        float s1 = (float)(s + 1);
        // FFMA with immediate multiplier (rt=1 on sm_103a)
        float g0 = fmaf(fmaf(fmaf(k3, s0, k2), s0, k1), s0, k0);
        float g1 = fmaf(fmaf(fmaf(k3, s1, k2), s1, k1), s1, k0);
        float e0, e1;
        asm("ex2.approx.f32 %0, %1;" : "=f"(e0) : "f"(g0));
        asm("ex2.approx.f32 %0, %1;" : "=f"(e1) : "f"(g1));
        if (s < n)     acc0 += e0;
        if (s + 1 < n) acc1 += e1;
    }
    return fmaf(0.08f, acc0 + acc1, 0.02f * (float)n);
}

__global__ void __launch_bounds__(256)
flow_cost_kernel(const float4* __restrict__ x1,
                 const float4* __restrict__ x2,
                 const float* __restrict__ pp,
                 float* __restrict__ out,
                 int n_pairs) {
    int i = blockIdx.x * blockDim.x + threadIdx.x;  // handles 2 pairs
    int base = 2 * i;
    if (base >= n_pairs) return;

    float p00 = __ldg(pp + 0), p01 = __ldg(pp + 1);
    float p10 = __ldg(pp + 2), p11 = __ldg(pp + 3);
    float p20 = __ldg(pp + 4), p21 = __ldg(pp + 5);

    if (base + 1 < n_pairs) {
        float4 a = x1[i];
        float4 b = x2[i];
        float c0 = pair_cost(a.x, a.y, b.x, b.y, p00, p01, p10, p11, p20, p21);
        float c1 = pair_cost(a.z, a.w, b.z, b.w, p00, p01, p10, p11, p20, p21);
        float2 r = make_float2(c0, c1);
        *reinterpret_cast<float2*>(out + base) = r;
    } else {
        const float2* x1s = reinterpret_cast<const float2*>(x1);
        const float2* x2s = reinterpret_cast<const float2*>(x2);
        float2 a = x1s[base];
        float2 b = x2s[base];
        out[base] = pair_cost(a.x, a.y, b.x, b.y, p00, p01, p10, p11, p20, p21);
    }
}

extern "C" void kernel_launch(void* const* d_in, const int* in_sizes, int n_in,
                              void* d_out, int out_size) {
    const float4* x1 = (const float4*)d_in[0];
    const float4* x2 = (const float4*)d_in[1];
    const float*  pp = (const float*)d_in[2];
    float* out = (float*)d_out;

    int n_pairs = out_size;
    int n_threads_total = (n_pairs + 1) / 2;
    int threads = 256;
    int blocks = (n_threads_total + threads - 1) / threads;
    flow_cost_kernel<<<blocks, threads>>>(x1, x2, pp, out, n_pairs);
}

// round 3
// speedup vs baseline: 1.3493x; 1.2119x over previous
#include <cuda_runtime.h>
#include <cstdint>

// FlowEmbedder cost, round 3: multiplicative-recurrence + f32x2 packing.
//
// cost_i = 0.02*n_i + 0.08 * sum_{s=0}^{n_i-1} 2^{g_i(s)}
//   g(s) = k0 + k1 s + k2 s^2 + k3 s^3   (k's include the -log2(e) scale)
//   e_{s+1} = e_s * r_s ; r_{s+1} = r_s * q_s ; q_{s+1} = q_s * w
//   seeds: e_0=2^{k0}, r_0=2^{k1+k2+k3}, q_0=2^{2k2+6k3}, w=2^{6k3}
// -> 4 ex2 per pair instead of 16 (MUFU was the hidden bottleneck).
// n_i: q = euc/0.1 via 3-op correctly-rounded (Markstein) division
// (fl(1/0.1f) == 10.0f exactly), mask_s = (q >= s), n = floor(q)+1 <= 15,
// so only steps 0..14 are ever live.
// Each thread processes 2 pairs, packed lane-wise into f32x2 (FMUL2/FFMA2).

typedef unsigned long long u64;

__device__ __forceinline__ u64 pk2(float lo, float hi) {
    u64 r; asm("mov.b64 %0, {%1, %2};" : "=l"(r) : "f"(lo), "f"(hi)); return r;
}
__device__ __forceinline__ void upk2(float& lo, float& hi, u64 v) {
    asm("mov.b64 {%0, %1}, %2;" : "=f"(lo), "=f"(hi) : "l"(v));
}
__device__ __forceinline__ u64 mul2(u64 a, u64 b) {
    u64 d; asm("mul.rn.f32x2 %0, %1, %2;" : "=l"(d) : "l"(a), "l"(b)); return d;
}
__device__ __forceinline__ u64 add2(u64 a, u64 b) {
    u64 d; asm("add.rn.f32x2 %0, %1, %2;" : "=l"(d) : "l"(a), "l"(b)); return d;
}
__device__ __forceinline__ u64 fma2(u64 a, u64 b, u64 c) {
    u64 d; asm("fma.rn.f32x2 %0, %1, %2, %3;" : "=l"(d) : "l"(a), "l"(b), "l"(c)); return d;
}
__device__ __forceinline__ u64 ex2_2(u64 g) {
    float a, b; upk2(a, b, g);
    asm("ex2.approx.f32 %0, %1;" : "=f"(a) : "f"(a));
    asm("ex2.approx.f32 %0, %1;" : "=f"(b) : "f"(b));
    return pk2(a, b);
}
__device__ __forceinline__ float rsq_ap(float x) {
    float r; asm("rsqrt.approx.f32 %0, %1;" : "=f"(r) : "f"(x)); return r;
}

__device__ __forceinline__ void cost2(float ax0, float ay0, float bx0, float by0,
                                      float ax1, float ay1, float bx1, float by1,
                                      const float* __restrict__ pp,
                                      float& cost0, float& cost1) {
    // ---- scalar per-pair prologue -------------------------------------
    float dx0 = bx0 - ax0, dy0 = by0 - ay0;
    float dx1 = bx1 - ax1, dy1 = by1 - ay1;
    float d2_0 = fmaf(dx0, dx0, dy0 * dy0);
    float d2_1 = fmaf(dx1, dx1, dy1 * dy1);
    float euc0 = __fsqrt_rn(d2_0);
    float euc1 = __fsqrt_rn(d2_1);

    // correctly-rounded euc/0.1 (== __fdiv_rn): seed fl(1/0.1f)=10.0f exactly
    float t0 = euc0 * 10.0f;
    float q0 = fmaf(fmaf(-0.1f, t0, euc0), 10.0f, t0);
    float t1 = euc1 * 10.0f;
    float q1 = fmaf(fmaf(-0.1f, t1, euc1), 10.0f, t1);
    float nf0 = floorf(q0) + 1.0f;
    float nf1 = floorf(q1) + 1.0f;

    // step direction * 0.1 (approx path, tolerance-loose)
    float rs0 = rsq_ap(d2_0), rs1 = rsq_ap(d2_1);
    float h0 = (0.1f * dx0) * rs0, g0 = (0.1f * dy0) * rs0;
    float h1 = (0.1f * dx1) * rs1, g1 = (0.1f * dy1) * rs1;

    // ---- packed coefficient pipeline ----------------------------------
    const float NL2E = -1.4426950408889634f;
    float p00 = NL2E * pp[0], p01 = NL2E * pp[1];
    float p10 = (3.0f * NL2E) * pp[2], p11 = (3.0f * NL2E) * pp[3];
    float p20 = (3.0f * NL2E) * pp[4], p21 = (3.0f * NL2E) * pp[5];
    u64 P00 = pk2(p00, p00), P01 = pk2(p01, p01);
    u64 P10 = pk2(p10, p10), P11 = pk2(p11, p11);
    u64 P20 = pk2(p20, p20), P21 = pk2(p21, p21);

    u64 DX = pk2(dx0, dx1), DY = pk2(dy0, dy1);
    u64 X = pk2(ax0, ax1), Y = pk2(ay0, ay1);
    u64 H = pk2(h0, h1), G = pk2(g0, g1);

    u64 C0 = fma2(P01, DY, mul2(P00, DX));
    u64 C1 = fma2(P11, DY, mul2(P10, DX));
    u64 C2 = fma2(P21, DY, mul2(P20, DX));

    u64 XX = mul2(X, X), XY = mul2(X, Y), YY = mul2(Y, Y);
    u64 HH = mul2(H, H), HG = mul2(H, G), GG = mul2(G, G);
    u64 c2yy = mul2(C2, YY);
    u64 c2gg = mul2(C2, GG);

    // k0 = X*(C0*XX + C1*XY + C2*YY), k3 = H*(C0*HH + C1*HG + C2*GG)
    u64 k0 = mul2(X, fma2(C0, XX, fma2(C1, XY, c2yy)));
    u64 k3 = mul2(H, fma2(C0, HH, fma2(C1, HG, c2gg)));

    u64 C0_3 = add2(C0, add2(C0, C0));
    u64 C1_2 = add2(C1, C1);
    u64 C2_2 = add2(C2, C2);

    // k1 = H*gx(X,Y) + G*gy(X,Y); k2 = X*gx(H,G) + Y*gy(H,G)
    u64 gx0 = fma2(C0_3, XX, fma2(C1_2, XY, c2yy));
    u64 gy0 = fma2(C1, XX, mul2(C2_2, XY));
    u64 k1 = fma2(G, gy0, mul2(H, gx0));
    u64 gx1 = fma2(C0_3, HH, fma2(C1_2, HG, c2gg));
    u64 gy1 = fma2(C1, HH, mul2(C2_2, HG));
    u64 k2 = fma2(Y, gy1, mul2(X, gx1));

    // ---- recurrence seeds ---------------------------------------------
    const u64 THREE2 = 0x4040000040400000ULL;  // {3.0f, 3.0f}
    const u64 SIX2   = 0x40C0000040C00000ULL;  // {6.0f, 6.0f}
    u64 DG = add2(k1, add2(k2, k3));           // k1+k2+k3
    u64 tt = fma2(k3, THREE2, k2);             // k2+3k3
    u64 D2G = add2(tt, tt);                    // 2k2+6k3
    u64 WW = mul2(k3, SIX2);                   // 6k3

    u64 E = ex2_2(k0);
    u64 R = ex2_2(DG);
    u64 Q = ex2_2(D2G);
    u64 W = ex2_2(WW);

    // ---- unrolled 15-step recurrence ----------------------------------
    float a0e = 0.0f, a0o = 0.0f, a1e = 0.0f, a1o = 0.0f;
#pragma unroll
    for (int s = 0; s < 15; ++s) {
        float e0, e1;
        upk2(e0, e1, E);
        if (s == 0) {
            a0e += e0;             // q >= 0 always (euc > 0)
            a1e += e1;
        } else {
            float sf = (float)s;
            if (q0 >= sf) { if (s & 1) a0o += e0; else a0e += e0; }
            if (q1 >= sf) { if (s & 1) a1o += e1; else a1e += e1; }
        }
        if (s < 14) E = mul2(E, R);
        if (s < 13) R = mul2(R, Q);
        if (s < 12) Q = mul2(Q, W);
    }

    cost0 = fmaf(0.08f, a0e + a0o, 0.02f * nf0);
    cost1 = fmaf(0.08f, a1e + a1o, 0.02f * nf1);
}

__global__ void __launch_bounds__(256)
flow_cost_kernel(const float4* __restrict__ x1,
                 const float4* __restrict__ x2,
                 const float* __restrict__ pp,
                 float* __restrict__ out,
                 int n_pairs) {
    int i = blockIdx.x * blockDim.x + threadIdx.x;  // 2 pairs per thread
    int base = 2 * i;
    if (base >= n_pairs) return;

    if (base + 1 < n_pairs) {
        float4 a = x1[i];
        float4 b = x2[i];
        float c0, c1;
        cost2(a.x, a.y, b.x, b.y, a.z, a.w, b.z, b.w, pp, c0, c1);
        *reinterpret_cast<float2*>(out + base) = make_float2(c0, c1);
    } else {
        // odd tail: duplicate the single pair into both packed lanes
        const float2* x1s = reinterpret_cast<const float2*>(x1);
        const float2* x2s = reinterpret_cast<const float2*>(x2);
        float2 a = x1s[base];
        float2 b = x2s[base];
        float c0, c1;
        cost2(a.x, a.y, b.x, b.y, a.x, a.y, b.x, b.y, pp, c0, c1);
        out[base] = c0;
    }
}

extern "C" void kernel_launch(void* const* d_in, const int* in_sizes, int n_in,
                              void* d_out, int out_size) {
    const float4* x1 = (const float4*)d_in[0];
    const float4* x2 = (const float4*)d_in[1];
    const float*  pp = (const float*)d_in[2];
    float* out = (float*)d_out;

    int n_pairs = out_size;
    int n_threads_total = (n_pairs + 1) / 2;
    int threads = 256;
    int blocks = (n_threads_total + threads - 1) / threads;
    flow_cost_kernel<<<blocks, threads>>>(x1, x2, pp, out, n_pairs);
}